// round 12
// baseline (speedup 1.0000x reference)
#include <cuda_runtime.h>
#include <math.h>

#define NB 32
#define NC 64
#define NN 1024
#define NK 10
#define NO 1024
#define NKC 640            // NK * NC
#define EPSN 1e-5f

// ---------------- scratch (device globals: allocation-free) ----------------
__device__ float g_xt[NB * NN * NC];            // x transposed: [b][n][c]
__device__ float g_xx[NB * NN];                 // sum of squares per point
__device__ float g_nd[NB * NN * NN];            // neg_dist (134 MB)
__device__ int   g_idx[NB * NN * NK];           // top-k indices
__device__ float g_feat[NB * NN * NKC];         // gathered features [b][n][k*64+c]
__device__ float g_y1[NB * NO * NKC];           // GEMM1 out [b][o][kc]
__device__ float g_y2[NB * NO * NKC];           // GEMM2 out
__device__ float g_a1[NO], g_c1[NO], g_a2[NO], g_c2[NO];  // BN scale/shift

// ---------------- transpose x (B,C,N) -> xt (B,N,C) ----------------
__global__ void transpose_kernel(const float* __restrict__ x) {
    __shared__ float tile[32][33];
    int b  = blockIdx.z;
    int c0 = blockIdx.y * 32;
    int n0 = blockIdx.x * 32;
    int tx = threadIdx.x, ty = threadIdx.y;   // 32 x 8
    const float* xb = x + b * NC * NN;
#pragma unroll
    for (int i = 0; i < 32; i += 8)
        tile[ty + i][tx] = xb[(c0 + ty + i) * NN + n0 + tx];
    __syncthreads();
    float* xtb = g_xt + b * NN * NC;
#pragma unroll
    for (int i = 0; i < 32; i += 8)
        xtb[(n0 + ty + i) * NC + c0 + tx] = tile[tx][ty + i];
}

// ---------------- xx[b,n]: L=16 strided-4 chains x4, pairwise tree-4 --------
// THIS ROUND'S ONLY CHANGE. acc_j = sum over c = j, j+4, ..., j+60 of
// fl(v^2), sequential muladd (no fma). Final: (a0+a2)+(a1+a3) — the
// 4-lane shfl(2,1) association of a 4-warp column reducer / unroll-4 SLP.
__global__ void xx_kernel(const float* __restrict__ x) {
    int t = blockIdx.x * blockDim.x + threadIdx.x;   // 32768 threads
    int b = t >> 10, n = t & 1023;
    const float* xb = x + b * NC * NN + n;
    float a0 = 0.f, a1 = 0.f, a2 = 0.f, a3 = 0.f;
#pragma unroll
    for (int i = 0; i < 16; i++) {
        float v0 = xb[(4 * i + 0) * NN];
        float v1 = xb[(4 * i + 1) * NN];
        float v2 = xb[(4 * i + 2) * NN];
        float v3 = xb[(4 * i + 3) * NN];
        a0 = __fadd_rn(a0, __fmul_rn(v0, v0));
        a1 = __fadd_rn(a1, __fmul_rn(v1, v1));
        a2 = __fadd_rn(a2, __fmul_rn(v2, v2));
        a3 = __fadd_rn(a3, __fmul_rn(v3, v3));
    }
    g_xx[t] = __fadd_rn(__fadd_rn(a0, a2), __fadd_rn(a1, a3));
}

// ---------------- neg_dist tiles: 64x64, chain inner (FROZEN, = Round 4) ----
__global__ void dist_kernel() {
    __shared__ float sn[64][65];
    __shared__ float sm[64][65];
    __shared__ float sxn[64], sxm[64];
    int b  = blockIdx.z;
    int n0 = blockIdx.y * 64, m0 = blockIdx.x * 64;
    int tid = threadIdx.x;
    const float* xt = g_xt + b * NN * NC;
    for (int i = tid; i < 4096; i += 256) {
        int r = i >> 6, c = i & 63;
        sn[r][c] = xt[(n0 + r) * NC + c];
        sm[r][c] = xt[(m0 + r) * NC + c];
    }
    if (tid < 64)            sxn[tid]      = g_xx[b * NN + n0 + tid];
    else if (tid < 128)      sxm[tid - 64] = g_xx[b * NN + m0 + tid - 64];
    __syncthreads();

    int tx = tid & 15, ty = tid >> 4;
    float acc[4][4] = {};
#pragma unroll
    for (int c = 0; c < 64; c++) {
        float rn[4], rm[4];
#pragma unroll
        for (int i = 0; i < 4; i++) { rn[i] = sn[ty * 4 + i][c]; rm[i] = sm[tx * 4 + i][c]; }
#pragma unroll
        for (int i = 0; i < 4; i++)
#pragma unroll
            for (int j = 0; j < 4; j++) acc[i][j] = __fmaf_rn(rn[i], rm[j], acc[i][j]);
    }
#pragma unroll
    for (int i = 0; i < 4; i++) {
        float xn = sxn[ty * 4 + i];
        float4 o;
        o.x = __fsub_rn(__fsub_rn(__fmul_rn(2.f, acc[i][0]), xn), sxm[tx * 4 + 0]);
        o.y = __fsub_rn(__fsub_rn(__fmul_rn(2.f, acc[i][1]), xn), sxm[tx * 4 + 1]);
        o.z = __fsub_rn(__fsub_rn(__fmul_rn(2.f, acc[i][2]), xn), sxm[tx * 4 + 2]);
        o.w = __fsub_rn(__fsub_rn(__fmul_rn(2.f, acc[i][3]), xn), sxm[tx * 4 + 3]);
        *(float4*)&g_nd[(size_t)(b * NN + n0 + ty * 4 + i) * NN + m0 + tx * 4] = o;
    }
}

// ---------------- top-K per row (warp per row, iterative argmax; FROZEN) ----
__global__ void topk_kernel() {
    int w    = (blockIdx.x * blockDim.x + threadIdx.x) >> 5;  // row id 0..32767
    int lane = threadIdx.x & 31;
    const float* row = g_nd + (size_t)w * NN;
    float v[32];
#pragma unroll
    for (int j = 0; j < 32; j++) v[j] = row[j * 32 + lane];
    int sel[NK];
#pragma unroll
    for (int t = 0; t < NK; t++) {
        float bv = -3.4e38f; int bi = 0x7fffffff;
#pragma unroll
        for (int j = 0; j < 32; j++) {
            int gi = j * 32 + lane;
            bool used = false;
#pragma unroll
            for (int s = 0; s < NK; s++) if (s < t && sel[s] == gi) used = true;
            if (!used && (v[j] > bv || (v[j] == bv && gi < bi))) { bv = v[j]; bi = gi; }
        }
#pragma unroll
        for (int off = 16; off; off >>= 1) {
            float ov = __shfl_xor_sync(0xffffffffu, bv, off);
            int   oi = __shfl_xor_sync(0xffffffffu, bi, off);
            if (ov > bv || (ov == bv && oi < bi)) { bv = ov; bi = oi; }
        }
        sel[t] = bi;
        if (lane == 0) g_idx[w * NK + t] = bi;
    }
}

// ---------------- gather feat[b][n][k*64+c] = xt[b][idx[b,n,k]][c] ----------------
__global__ void gather_kernel() {
    int t = blockIdx.x * blockDim.x + threadIdx.x;
    int c = t & 63;
    int k = (t >> 6) % NK;
    int n = (t / NKC) & 1023;
    int b = t / (NN * NKC);
    int gi = g_idx[((b << 10) + n) * NK + k];
    g_feat[t] = g_xt[((b << 10) + gi) * NC + c];
}

// ---------------- layer GEMMs: plain fp32 ------------------------------------
// C[b] (1024x640) = A (1024x1024) * Bmat[b] (1024x640)
template <int STAGE>
__global__ void gemm_kernel(const float* __restrict__ A) {
    __shared__ float As[8][128];
    __shared__ float Bs[8][128];
    int tid = threadIdx.x;                     // 256
    int bz  = blockIdx.z;
    const float* Bm = (STAGE == 1) ? g_feat : g_y1;
    float*       Cm = (STAGE == 1) ? g_y1   : g_y2;

    const float* Ab = A + blockIdx.y * 128 * 1024;
    const float* Bb = Bm + (size_t)bz * (NO * NKC) + blockIdx.x * 128;
    float*       Cb = Cm + (size_t)bz * (NO * NKC) + (blockIdx.y * 128) * NKC + blockIdx.x * 128;

    int row_a = tid >> 1, ka = (tid & 1) * 4;
    int kb = tid >> 5, col_b = (tid & 31) * 4;
    int tr = (tid >> 4) * 8, tcl = (tid & 15) * 8;

    float acc[8][8] = {};
    for (int kt = 0; kt < 128; kt++) {
        float4 av = *(const float4*)(Ab + row_a * 1024 + kt * 8 + ka);
        As[ka + 0][row_a] = av.x; As[ka + 1][row_a] = av.y;
        As[ka + 2][row_a] = av.z; As[ka + 3][row_a] = av.w;
        int kr = kt * 8 + kb;
        float4 bv = *(const float4*)(Bb + (size_t)kr * NKC + col_b);
        if (STAGE == 2) {
            float a = g_a1[kr], c = g_c1[kr];
            bv.x = fmaxf(fmaf(a, bv.x, c), 0.f);
            bv.y = fmaxf(fmaf(a, bv.y, c), 0.f);
            bv.z = fmaxf(fmaf(a, bv.z, c), 0.f);
            bv.w = fmaxf(fmaf(a, bv.w, c), 0.f);
        }
        *(float4*)&Bs[kb][col_b] = bv;
        __syncthreads();
#pragma unroll
        for (int kk = 0; kk < 8; kk++) {
            float ar[8], br[8];
            *(float4*)(ar)     = *(float4*)&As[kk][tr];
            *(float4*)(ar + 4) = *(float4*)&As[kk][tr + 4];
            *(float4*)(br)     = *(float4*)&Bs[kk][tcl];
            *(float4*)(br + 4) = *(float4*)&Bs[kk][tcl + 4];
#pragma unroll
            for (int i = 0; i < 8; i++)
#pragma unroll
                for (int j = 0; j < 8; j++) acc[i][j] = fmaf(ar[i], br[j], acc[i][j]);
        }
        __syncthreads();
    }
#pragma unroll
    for (int i = 0; i < 8; i++) {
        *(float4*)&Cb[(tr + i) * NKC + tcl]     = *(float4*)&acc[i][0];
        *(float4*)&Cb[(tr + i) * NKC + tcl + 4] = *(float4*)&acc[i][4];
    }
}

// ---------------- BN stats per channel o: a = gamma*rsqrt(var+eps), c = beta - mean*a
__global__ void bn_stats_kernel(const float* __restrict__ gamma,
                                const float* __restrict__ beta, int which) {
    const float* Y = which ? g_y2 : g_y1;
    int o = blockIdx.x, tid = threadIdx.x;
    float s = 0.f, sq = 0.f;
    for (int j = tid; j < NB * NKC; j += 256) {
        int b = j / NKC, kc = j - b * NKC;
        float v = Y[((size_t)b * NO + o) * NKC + kc];
        s += v; sq = fmaf(v, v, sq);
    }
    __shared__ float ss[256], s2[256];
    ss[tid] = s; s2[tid] = sq;
    __syncthreads();
    for (int st = 128; st; st >>= 1) {
        if (tid < st) { ss[tid] += ss[tid + st]; s2[tid] += s2[tid + st]; }
        __syncthreads();
    }
    if (tid == 0) {
        float cnt  = (float)(NB * NKC);
        float mean = ss[0] / cnt;
        float var  = fmaxf(s2[0] / cnt - mean * mean, 0.f);
        float ai   = gamma[o] * rsqrtf(var + EPSN);
        if (which) { g_a2[o] = ai; g_c2[o] = beta[o] - mean * ai; }
        else       { g_a1[o] = ai; g_c1[o] = beta[o] - mean * ai; }
    }
}

// ---------------- out[b,o,c] = max_k relu(a2*y2 + c2) ----------------
__global__ void max_kernel(float* __restrict__ out) {
    int t = blockIdx.x * blockDim.x + threadIdx.x;
    int c = t & 63;
    int o = (t >> 6) & 1023;
    int b = t >> 16;
    const float* y = g_y2 + ((size_t)(b * NO + o)) * NKC + c;
    float a = g_a2[o], cc = g_c2[o];
    float m = -3.4e38f;
#pragma unroll
    for (int k = 0; k < NK; k++) m = fmaxf(m, fmaf(a, y[k * 64], cc));
    out[t] = fmaxf(m, 0.f);
}

// ---------------- launch ----------------
extern "C" void kernel_launch(void* const* d_in, const int* in_sizes, int n_in,
                              void* d_out, int out_size) {
    const float* x      = (const float*)d_in[0];
    const float* w1     = (const float*)d_in[1];
    // b1 = d_in[2], b2 = d_in[6]: zeros AND cancelled by BN mean-subtraction
    const float* gamma1 = (const float*)d_in[3];
    const float* beta1  = (const float*)d_in[4];
    const float* w2     = (const float*)d_in[5];
    const float* gamma2 = (const float*)d_in[7];
    const float* beta2  = (const float*)d_in[8];
    float* out = (float*)d_out;

    transpose_kernel<<<dim3(32, 2, 32), dim3(32, 8)>>>(x);
    xx_kernel<<<128, 256>>>(x);
    dist_kernel<<<dim3(16, 16, 32), 256>>>();
    topk_kernel<<<4096, 256>>>();
    gather_kernel<<<81920, 256>>>();
    gemm_kernel<1><<<dim3(5, 8, 32), 256>>>(w1);
    bn_stats_kernel<<<1024, 256>>>(gamma1, beta1, 0);
    gemm_kernel<2><<<dim3(5, 8, 32), 256>>>(w2);
    bn_stats_kernel<<<1024, 256>>>(gamma2, beta2, 1);
    max_kernel<<<8192, 256>>>(out);
}

// round 13
// speedup vs baseline: 2.4505x; 2.4505x over previous
#include <cuda_runtime.h>
#include <math.h>
#include <stdint.h>

#define NB 32
#define NC 64
#define NN 1024
#define NK 10
#define NO 1024
#define NKC 640            // NK * NC
#define EPSN 1e-5f

// TF32 quantization (cublas-style input rounding)
__device__ __forceinline__ float tf32r(float a) {
    asm("cvt.rna.tf32.f32 %0, %1;" : "=f"(a) : "f"(a));
    return a;
}

// ---------------- scratch (device globals: allocation-free) ----------------
__device__ float g_xt[NB * NN * NC];            // x transposed: [b][n][c]
__device__ float g_xx[NB * NN];                 // sum of squares per point
__device__ float g_nd[NB * NN * NN];            // neg_dist (134 MB)
__device__ int   g_idx[NB * NN * NK];           // top-k indices
__device__ float g_feat[NB * NN * NKC];         // gathered features [b][n][k*64+c]
__device__ float g_y1[NB * NO * NKC];           // GEMM1 out [b][o][kc]
__device__ float g_y2[NB * NO * NKC];           // GEMM2 out
__device__ float g_a1[NO], g_c1[NO], g_a2[NO], g_c2[NO];  // BN scale/shift

// ---------------- transpose x (B,C,N) -> xt (B,N,C) ----------------
__global__ void transpose_kernel(const float* __restrict__ x) {
    __shared__ float tile[32][33];
    int b  = blockIdx.z;
    int c0 = blockIdx.y * 32;
    int n0 = blockIdx.x * 32;
    int tx = threadIdx.x, ty = threadIdx.y;   // 32 x 8
    const float* xb = x + b * NC * NN;
#pragma unroll
    for (int i = 0; i < 32; i += 8)
        tile[ty + i][tx] = xb[(c0 + ty + i) * NN + n0 + tx];
    __syncthreads();
    float* xtb = g_xt + b * NN * NC;
#pragma unroll
    for (int i = 0; i < 32; i += 8)
        xtb[(n0 + ty + i) * NC + c0 + tx] = tile[tx][ty + i];
}

// ---------------- xx[b,n]: WINNING RECIPE (bit-frozen forever) --------------
// 4 accumulators, stride-4 chains of length 16, combine (a0+a2)+(a1+a3).
__global__ void xx_kernel(const float* __restrict__ x) {
    int t = blockIdx.x * blockDim.x + threadIdx.x;   // 32768 threads
    int b = t >> 10, n = t & 1023;
    const float* xb = x + b * NC * NN + n;
    float a0 = 0.f, a1 = 0.f, a2 = 0.f, a3 = 0.f;
#pragma unroll
    for (int i = 0; i < 16; i++) {
        float v0 = xb[(4 * i + 0) * NN];
        float v1 = xb[(4 * i + 1) * NN];
        float v2 = xb[(4 * i + 2) * NN];
        float v3 = xb[(4 * i + 3) * NN];
        a0 = __fadd_rn(a0, __fmul_rn(v0, v0));
        a1 = __fadd_rn(a1, __fmul_rn(v1, v1));
        a2 = __fadd_rn(a2, __fmul_rn(v2, v2));
        a3 = __fadd_rn(a3, __fmul_rn(v3, v3));
    }
    g_xx[t] = __fadd_rn(__fadd_rn(a0, a2), __fadd_rn(a1, a3));
}

// ---------------- neg_dist tiles: 64x64, chain inner (bit-frozen) -----------
__global__ void dist_kernel() {
    __shared__ float sn[64][65];
    __shared__ float sm[64][65];
    __shared__ float sxn[64], sxm[64];
    int b  = blockIdx.z;
    int n0 = blockIdx.y * 64, m0 = blockIdx.x * 64;
    int tid = threadIdx.x;
    const float* xt = g_xt + b * NN * NC;
    for (int i = tid; i < 4096; i += 256) {
        int r = i >> 6, c = i & 63;
        sn[r][c] = xt[(n0 + r) * NC + c];
        sm[r][c] = xt[(m0 + r) * NC + c];
    }
    if (tid < 64)            sxn[tid]      = g_xx[b * NN + n0 + tid];
    else if (tid < 128)      sxm[tid - 64] = g_xx[b * NN + m0 + tid - 64];
    __syncthreads();

    int tx = tid & 15, ty = tid >> 4;
    float acc[4][4] = {};
#pragma unroll
    for (int c = 0; c < 64; c++) {
        float rn[4], rm[4];
#pragma unroll
        for (int i = 0; i < 4; i++) { rn[i] = sn[ty * 4 + i][c]; rm[i] = sm[tx * 4 + i][c]; }
#pragma unroll
        for (int i = 0; i < 4; i++)
#pragma unroll
            for (int j = 0; j < 4; j++) acc[i][j] = __fmaf_rn(rn[i], rm[j], acc[i][j]);
    }
#pragma unroll
    for (int i = 0; i < 4; i++) {
        float xn = sxn[ty * 4 + i];
        float4 o;
        o.x = __fsub_rn(__fsub_rn(__fmul_rn(2.f, acc[i][0]), xn), sxm[tx * 4 + 0]);
        o.y = __fsub_rn(__fsub_rn(__fmul_rn(2.f, acc[i][1]), xn), sxm[tx * 4 + 1]);
        o.z = __fsub_rn(__fsub_rn(__fmul_rn(2.f, acc[i][2]), xn), sxm[tx * 4 + 2]);
        o.w = __fsub_rn(__fsub_rn(__fmul_rn(2.f, acc[i][3]), xn), sxm[tx * 4 + 3]);
        *(float4*)&g_nd[(size_t)(b * NN + n0 + ty * 4 + i) * NN + m0 + tx * 4] = o;
    }
}

// ---------------- top-K: bitmask rewrite (selection order bit-identical) ----
// Per-lane 32-bit used-mask replaces the O(NK^2*32) sel-scan. Within a lane,
// ascending-j strict-> keeps lowest gi on ties (same as before); cross-lane
// reduce unchanged. Same indices, ~1/5 the ALU work, regs 117 -> ~45.
__global__ void topk_kernel() {
    int w    = (blockIdx.x * blockDim.x + threadIdx.x) >> 5;  // row id 0..32767
    int lane = threadIdx.x & 31;
    const float* row = g_nd + (size_t)w * NN;
    float v[32];
#pragma unroll
    for (int j = 0; j < 32; j++) v[j] = row[j * 32 + lane];
    unsigned used = 0u;
#pragma unroll
    for (int t = 0; t < NK; t++) {
        float bv = -3.4e38f; int bj = 0;
#pragma unroll
        for (int j = 0; j < 32; j++)
            if (!((used >> j) & 1u) && v[j] > bv) { bv = v[j]; bj = j; }
        int bi = bj * 32 + lane;
#pragma unroll
        for (int off = 16; off; off >>= 1) {
            float ov = __shfl_xor_sync(0xffffffffu, bv, off);
            int   oi = __shfl_xor_sync(0xffffffffu, bi, off);
            if (ov > bv || (ov == bv && oi < bi)) { bv = ov; bi = oi; }
        }
        if ((bi & 31) == lane) used |= 1u << (bi >> 5);
        if (lane == 0) g_idx[w * NK + t] = bi;
    }
}

// ---------------- gather feat[b][n][k*64+c] = xt[b][idx[b,n,k]][c] ----------------
__global__ void gather_kernel() {
    int t = blockIdx.x * blockDim.x + threadIdx.x;
    int c = t & 63;
    int k = (t >> 6) % NK;
    int n = (t / NKC) & 1023;
    int b = t / (NN * NKC);
    int gi = g_idx[((b << 10) + n) * NK + k];
    g_feat[t] = g_xt[((b << 10) + gi) * NC + c];
}

// ---------------- layer GEMMs on TENSOR CORES: mma.sync m16n8k8 TF32 --------
// C[b](1024x640) = A(1024x1024) * Bmat[b](1024x640), fp32 accumulation.
// TF32 layer noise measured in R7: 3.0e-4 << 1e-3 threshold.
// Block: 128(o) x 64(kc), 8 warps (4 along o, 2 along kc), warp tile 32x32.
__device__ __forceinline__ void mma_tf32(float* d, const uint32_t* a,
                                         const uint32_t* b, const float* c) {
    asm volatile(
        "mma.sync.aligned.m16n8k8.row.col.f32.tf32.tf32.f32 "
        "{%0,%1,%2,%3}, {%4,%5,%6,%7}, {%8,%9}, {%10,%11,%12,%13};"
        : "=f"(d[0]), "=f"(d[1]), "=f"(d[2]), "=f"(d[3])
        : "r"(a[0]), "r"(a[1]), "r"(a[2]), "r"(a[3]),
          "r"(b[0]), "r"(b[1]),
          "f"(c[0]), "f"(c[1]), "f"(c[2]), "f"(c[3]));
}

template <int STAGE>
__global__ void gemm_mma_kernel(const float* __restrict__ A) {
    __shared__ float As[128][36];   // [o][k]  pad 4 -> conflict-free frags
    __shared__ float Bs[32][72];    // [k][kc] pad 8 -> conflict-free frags
    const float* Bm = (STAGE == 1) ? g_feat : g_y1;
    float*       Cm = (STAGE == 1) ? g_y1   : g_y2;

    int tid = threadIdx.x;                    // 256
    int bz  = blockIdx.z;
    int o0  = blockIdx.y * 128;
    int kc0 = blockIdx.x * 64;
    const float* Ab = A + (size_t)o0 * 1024;
    const float* Bb = Bm + (size_t)bz * (NO * NKC) + kc0;
    float*       Cb = Cm + (size_t)bz * (NO * NKC) + (size_t)o0 * NKC + kc0;

    int warp = tid >> 5, lane = tid & 31;
    int warp_o = warp & 3, warp_n = warp >> 2;   // 4 x 2 warp grid
    int g = lane >> 2, tg = lane & 3;

    float acc[2][4][4];
#pragma unroll
    for (int mt = 0; mt < 2; mt++)
#pragma unroll
        for (int nt = 0; nt < 4; nt++)
#pragma unroll
            for (int r = 0; r < 4; r++) acc[mt][nt][r] = 0.f;

    for (int kt = 0; kt < 32; kt++) {
        int k0 = kt * 32;
        // A tile 128x32 (4 float4 per thread), tf32-quantized into As
#pragma unroll
        for (int p = 0; p < 4; p++) {
            int idx = p * 256 + tid;            // 0..1023
            int row = idx >> 3;
            int col = (idx & 7) * 4;
            float4 v = *(const float4*)(Ab + (size_t)row * 1024 + k0 + col);
            As[row][col + 0] = tf32r(v.x); As[row][col + 1] = tf32r(v.y);
            As[row][col + 2] = tf32r(v.z); As[row][col + 3] = tf32r(v.w);
        }
        // B tile 32x64 (2 float4 per thread); STAGE2 applies BN-ReLU per n-row
#pragma unroll
        for (int p = 0; p < 2; p++) {
            int idx = p * 256 + tid;            // 0..511
            int row = idx >> 4;
            int col = (idx & 15) * 4;
            int n   = k0 + row;
            float4 v = *(const float4*)(Bb + (size_t)n * NKC + col);
            if (STAGE == 2) {
                float a = g_a1[n], c = g_c1[n];
                v.x = fmaxf(fmaf(a, v.x, c), 0.f);
                v.y = fmaxf(fmaf(a, v.y, c), 0.f);
                v.z = fmaxf(fmaf(a, v.z, c), 0.f);
                v.w = fmaxf(fmaf(a, v.w, c), 0.f);
            }
            Bs[row][col + 0] = tf32r(v.x); Bs[row][col + 1] = tf32r(v.y);
            Bs[row][col + 2] = tf32r(v.z); Bs[row][col + 3] = tf32r(v.w);
        }
        __syncthreads();

#pragma unroll
        for (int s = 0; s < 4; s++) {           // k-steps of 8 within tile
            int kr = s * 8;
            uint32_t af[2][4], bf[4][2];
#pragma unroll
            for (int mt = 0; mt < 2; mt++) {
                int o = warp_o * 32 + mt * 16;
                af[mt][0] = __float_as_uint(As[o + g    ][kr + tg    ]);
                af[mt][1] = __float_as_uint(As[o + g + 8][kr + tg    ]);
                af[mt][2] = __float_as_uint(As[o + g    ][kr + tg + 4]);
                af[mt][3] = __float_as_uint(As[o + g + 8][kr + tg + 4]);
            }
#pragma unroll
            for (int nt = 0; nt < 4; nt++) {
                int col = warp_n * 32 + nt * 8 + g;
                bf[nt][0] = __float_as_uint(Bs[kr + tg    ][col]);
                bf[nt][1] = __float_as_uint(Bs[kr + tg + 4][col]);
            }
#pragma unroll
            for (int mt = 0; mt < 2; mt++)
#pragma unroll
                for (int nt = 0; nt < 4; nt++)
                    mma_tf32(acc[mt][nt], af[mt], bf[nt], acc[mt][nt]);
        }
        __syncthreads();
    }

    // epilogue: c0,c1 -> (row g, cols 2tg,2tg+1); c2,c3 -> row g+8
#pragma unroll
    for (int mt = 0; mt < 2; mt++) {
        int row = warp_o * 32 + mt * 16 + g;
#pragma unroll
        for (int nt = 0; nt < 4; nt++) {
            int col = warp_n * 32 + nt * 8 + tg * 2;
            *(float2*)&Cb[(size_t)(row    ) * NKC + col] =
                make_float2(acc[mt][nt][0], acc[mt][nt][1]);
            *(float2*)&Cb[(size_t)(row + 8) * NKC + col] =
                make_float2(acc[mt][nt][2], acc[mt][nt][3]);
        }
    }
}

// ---------------- BN stats per channel o: a = gamma*rsqrt(var+eps), c = beta - mean*a
__global__ void bn_stats_kernel(const float* __restrict__ gamma,
                                const float* __restrict__ beta, int which) {
    const float* Y = which ? g_y2 : g_y1;
    int o = blockIdx.x, tid = threadIdx.x;
    float s = 0.f, sq = 0.f;
    for (int j = tid; j < NB * NKC; j += 256) {
        int b = j / NKC, kc = j - b * NKC;
        float v = Y[((size_t)b * NO + o) * NKC + kc];
        s += v; sq = fmaf(v, v, sq);
    }
    __shared__ float ss[256], s2[256];
    ss[tid] = s; s2[tid] = sq;
    __syncthreads();
    for (int st = 128; st; st >>= 1) {
        if (tid < st) { ss[tid] += ss[tid + st]; s2[tid] += s2[tid + st]; }
        __syncthreads();
    }
    if (tid == 0) {
        float cnt  = (float)(NB * NKC);
        float mean = ss[0] / cnt;
        float var  = fmaxf(s2[0] / cnt - mean * mean, 0.f);
        float ai   = gamma[o] * rsqrtf(var + EPSN);
        if (which) { g_a2[o] = ai; g_c2[o] = beta[o] - mean * ai; }
        else       { g_a1[o] = ai; g_c1[o] = beta[o] - mean * ai; }
    }
}

// ---------------- out[b,o,c] = max_k relu(a2*y2 + c2) ----------------
__global__ void max_kernel(float* __restrict__ out) {
    int t = blockIdx.x * blockDim.x + threadIdx.x;
    int c = t & 63;
    int o = (t >> 6) & 1023;
    int b = t >> 16;
    const float* y = g_y2 + ((size_t)(b * NO + o)) * NKC + c;
    float a = g_a2[o], cc = g_c2[o];
    float m = -3.4e38f;
#pragma unroll
    for (int k = 0; k < NK; k++) m = fmaxf(m, fmaf(a, y[k * 64], cc));
    out[t] = fmaxf(m, 0.f);
}

// ---------------- launch ----------------
extern "C" void kernel_launch(void* const* d_in, const int* in_sizes, int n_in,
                              void* d_out, int out_size) {
    const float* x      = (const float*)d_in[0];
    const float* w1     = (const float*)d_in[1];
    // b1 = d_in[2], b2 = d_in[6]: zeros AND cancelled by BN mean-subtraction
    const float* gamma1 = (const float*)d_in[3];
    const float* beta1  = (const float*)d_in[4];
    const float* w2     = (const float*)d_in[5];
    const float* gamma2 = (const float*)d_in[7];
    const float* beta2  = (const float*)d_in[8];
    float* out = (float*)d_out;

    transpose_kernel<<<dim3(32, 2, 32), dim3(32, 8)>>>(x);
    xx_kernel<<<128, 256>>>(x);
    dist_kernel<<<dim3(16, 16, 32), 256>>>();
    topk_kernel<<<4096, 256>>>();
    gather_kernel<<<81920, 256>>>();
    gemm_mma_kernel<1><<<dim3(10, 8, 32), 256>>>(w1);
    bn_stats_kernel<<<1024, 256>>>(gamma1, beta1, 0);
    gemm_mma_kernel<2><<<dim3(10, 8, 32), 256>>>(w2);
    bn_stats_kernel<<<1024, 256>>>(gamma2, beta2, 1);
    max_kernel<<<8192, 256>>>(out);
}

// round 14
// speedup vs baseline: 2.8472x; 1.1619x over previous
#include <cuda_runtime.h>
#include <math.h>
#include <stdint.h>

#define NB 32
#define NC 64
#define NN 1024
#define NK 10
#define NO 1024
#define NKC 640            // NK * NC
#define EPSN 1e-5f

// TF32 quantization (cublas-style input rounding)
__device__ __forceinline__ float tf32r(float a) {
    asm("cvt.rna.tf32.f32 %0, %1;" : "=f"(a) : "f"(a));
    return a;
}

// ---------------- scratch (device globals: allocation-free) ----------------
__device__ float g_xt[NB * NN * NC];            // x transposed: [b][n][c]
__device__ float g_xx[NB * NN];                 // sum of squares per point
__device__ float g_nd[NB * NN * NN];            // neg_dist (134 MB)
__device__ int   g_idx[NB * NN * NK];           // top-k indices
__device__ float g_feat[NB * NN * NKC];         // gathered features [b][n][k*64+c]
__device__ float g_y1[NB * NO * NKC];           // GEMM1 out [b][o][kc]
__device__ float g_y2[NB * NO * NKC];           // GEMM2 out
__device__ float g_a1[NO], g_c1[NO], g_a2[NO], g_c2[NO];  // BN scale/shift

// ---------------- transpose x (B,C,N) -> xt (B,N,C) ----------------
__global__ void transpose_kernel(const float* __restrict__ x) {
    __shared__ float tile[32][33];
    int b  = blockIdx.z;
    int c0 = blockIdx.y * 32;
    int n0 = blockIdx.x * 32;
    int tx = threadIdx.x, ty = threadIdx.y;   // 32 x 8
    const float* xb = x + b * NC * NN;
#pragma unroll
    for (int i = 0; i < 32; i += 8)
        tile[ty + i][tx] = xb[(c0 + ty + i) * NN + n0 + tx];
    __syncthreads();
    float* xtb = g_xt + b * NN * NC;
#pragma unroll
    for (int i = 0; i < 32; i += 8)
        xtb[(n0 + ty + i) * NC + c0 + tx] = tile[tx][ty + i];
}

// ---------------- xx[b,n]: WINNING RECIPE (bit-frozen) ----------------------
__global__ void xx_kernel(const float* __restrict__ x) {
    int t = blockIdx.x * blockDim.x + threadIdx.x;   // 32768 threads
    int b = t >> 10, n = t & 1023;
    const float* xb = x + b * NC * NN + n;
    float a0 = 0.f, a1 = 0.f, a2 = 0.f, a3 = 0.f;
#pragma unroll
    for (int i = 0; i < 16; i++) {
        float v0 = xb[(4 * i + 0) * NN];
        float v1 = xb[(4 * i + 1) * NN];
        float v2 = xb[(4 * i + 2) * NN];
        float v3 = xb[(4 * i + 3) * NN];
        a0 = __fadd_rn(a0, __fmul_rn(v0, v0));
        a1 = __fadd_rn(a1, __fmul_rn(v1, v1));
        a2 = __fadd_rn(a2, __fmul_rn(v2, v2));
        a3 = __fadd_rn(a3, __fmul_rn(v3, v3));
    }
    g_xx[t] = __fadd_rn(__fadd_rn(a0, a2), __fadd_rn(a1, a3));
}

// ---------------- neg_dist: SYMMETRIC tiles (bit-exact halving) -------------
// Only 136 upper-triangle (ti<=tj) 64x64 tile pairs per batch.
// Forward cell (row,col): ((2*acc - xx_row) - xx_col)   [frozen recipe]
// Mirror  cell (col,row): ((2*acc - xx_col) - xx_row)   [same recipe, roles swapped]
// fmaf(a,b,acc)==fmaf(b,a,acc) bitwise => mirror inner is bit-identical.
__global__ void dist_kernel() {
    __shared__ float sn[64][65];
    __shared__ float sm[64][65];   // reused as mirror staging after compute
    __shared__ float sxn[64], sxm[64];
    int b = blockIdx.z;
    // unrank pair index -> (ti <= tj)
    int p = blockIdx.x;
    int ti = 0;
    while (p >= 16 - ti) { p -= 16 - ti; ti++; }
    int tj = ti + p;
    int n0 = ti * 64, m0 = tj * 64;

    int tid = threadIdx.x;
    const float* xt = g_xt + b * NN * NC;
    for (int i = tid; i < 4096; i += 256) {
        int r = i >> 6, c = i & 63;
        sn[r][c] = xt[(n0 + r) * NC + c];
        sm[r][c] = xt[(m0 + r) * NC + c];
    }
    if (tid < 64)            sxn[tid]      = g_xx[b * NN + n0 + tid];
    else if (tid < 128)      sxm[tid - 64] = g_xx[b * NN + m0 + tid - 64];
    __syncthreads();

    int tx = tid & 15, ty = tid >> 4;
    float acc[4][4] = {};
#pragma unroll
    for (int c = 0; c < 64; c++) {
        float rn[4], rm[4];
#pragma unroll
        for (int i = 0; i < 4; i++) { rn[i] = sn[ty * 4 + i][c]; rm[i] = sm[tx * 4 + i][c]; }
#pragma unroll
        for (int i = 0; i < 4; i++)
#pragma unroll
            for (int j = 0; j < 4; j++) acc[i][j] = __fmaf_rn(rn[i], rm[j], acc[i][j]);
    }
    // forward tile write (rows n0+, cols m0+)
#pragma unroll
    for (int i = 0; i < 4; i++) {
        float xn = sxn[ty * 4 + i];
        float4 o;
        o.x = __fsub_rn(__fsub_rn(__fmul_rn(2.f, acc[i][0]), xn), sxm[tx * 4 + 0]);
        o.y = __fsub_rn(__fsub_rn(__fmul_rn(2.f, acc[i][1]), xn), sxm[tx * 4 + 1]);
        o.z = __fsub_rn(__fsub_rn(__fmul_rn(2.f, acc[i][2]), xn), sxm[tx * 4 + 2]);
        o.w = __fsub_rn(__fsub_rn(__fmul_rn(2.f, acc[i][3]), xn), sxm[tx * 4 + 3]);
        *(float4*)&g_nd[(size_t)(b * NN + n0 + ty * 4 + i) * NN + m0 + tx * 4] = o;
    }
    if (ti == tj) return;
    // mirror tile: stage transposed values into sm, then write coalesced
    __syncthreads();   // all compute reads of sm complete
#pragma unroll
    for (int i = 0; i < 4; i++) {
        float xn = sxn[ty * 4 + i];
#pragma unroll
        for (int j = 0; j < 4; j++) {
            float mv = __fsub_rn(__fsub_rn(__fmul_rn(2.f, acc[i][j]),
                                           sxm[tx * 4 + j]), xn);
            sm[tx * 4 + j][ty * 4 + i] = mv;
        }
    }
    __syncthreads();
    for (int i = tid; i < 4096; i += 256) {
        int r = i >> 6, c = i & 63;
        g_nd[(size_t)(b * NN + m0 + r) * NN + n0 + c] = sm[r][c];
    }
}

// ---------------- top-K: bitmask argmax (bit-frozen selection) --------------
__global__ void topk_kernel() {
    int w    = (blockIdx.x * blockDim.x + threadIdx.x) >> 5;  // row id 0..32767
    int lane = threadIdx.x & 31;
    const float* row = g_nd + (size_t)w * NN;
    float v[32];
#pragma unroll
    for (int j = 0; j < 32; j++) v[j] = row[j * 32 + lane];
    unsigned used = 0u;
#pragma unroll
    for (int t = 0; t < NK; t++) {
        float bv = -3.4e38f; int bj = 0;
#pragma unroll
        for (int j = 0; j < 32; j++)
            if (!((used >> j) & 1u) && v[j] > bv) { bv = v[j]; bj = j; }
        int bi = bj * 32 + lane;
#pragma unroll
        for (int off = 16; off; off >>= 1) {
            float ov = __shfl_xor_sync(0xffffffffu, bv, off);
            int   oi = __shfl_xor_sync(0xffffffffu, bi, off);
            if (ov > bv || (ov == bv && oi < bi)) { bv = ov; bi = oi; }
        }
        if ((bi & 31) == lane) used |= 1u << (bi >> 5);
        if (lane == 0) g_idx[w * NK + t] = bi;
    }
}

// ---------------- gather feat[b][n][k*64+c] = xt[b][idx[b,n,k]][c] ----------------
__global__ void gather_kernel() {
    int t = blockIdx.x * blockDim.x + threadIdx.x;
    int c = t & 63;
    int k = (t >> 6) % NK;
    int n = (t / NKC) & 1023;
    int b = t / (NN * NKC);
    int gi = g_idx[((b << 10) + n) * NK + k];
    g_feat[t] = g_xt[((b << 10) + gi) * NC + c];
}

// ---------------- layer GEMMs: mma.sync TF32, 2 BATCHES PER BLOCK -----------
// A (w) tile loaded once, reused for two batches' B tiles -> A L2 traffic
// halved; per-k-tile gmem drops below the LTS cap. Math per batch unchanged.
__device__ __forceinline__ void mma_tf32(float* d, const uint32_t* a,
                                         const uint32_t* b, const float* c) {
    asm volatile(
        "mma.sync.aligned.m16n8k8.row.col.f32.tf32.tf32.f32 "
        "{%0,%1,%2,%3}, {%4,%5,%6,%7}, {%8,%9}, {%10,%11,%12,%13};"
        : "=f"(d[0]), "=f"(d[1]), "=f"(d[2]), "=f"(d[3])
        : "r"(a[0]), "r"(a[1]), "r"(a[2]), "r"(a[3]),
          "r"(b[0]), "r"(b[1]),
          "f"(c[0]), "f"(c[1]), "f"(c[2]), "f"(c[3]));
}

template <int STAGE>
__global__ __launch_bounds__(256) void gemm_mma_kernel(const float* __restrict__ A) {
    __shared__ float As[128][36];      // [o][k]
    __shared__ float Bs[2][32][72];    // [q][k][kc]
    const float* Bm = (STAGE == 1) ? g_feat : g_y1;
    float*       Cm = (STAGE == 1) ? g_y1   : g_y2;

    int tid = threadIdx.x;                    // 256
    int bz0 = blockIdx.z * 2;                 // batches bz0, bz0+1
    int o0  = blockIdx.y * 128;
    int kc0 = blockIdx.x * 64;
    const float* Ab = A + (size_t)o0 * 1024;
    const float* Bb0 = Bm + (size_t)(bz0    ) * (NO * NKC) + kc0;
    const float* Bb1 = Bm + (size_t)(bz0 + 1) * (NO * NKC) + kc0;

    int warp = tid >> 5, lane = tid & 31;
    int warp_o = warp & 3, warp_n = warp >> 2;   // 4 x 2 warp grid
    int g = lane >> 2, tg = lane & 3;

    float acc[2][2][4][4];                    // [q][mt][nt][reg]
#pragma unroll
    for (int q = 0; q < 2; q++)
#pragma unroll
        for (int mt = 0; mt < 2; mt++)
#pragma unroll
            for (int nt = 0; nt < 4; nt++)
#pragma unroll
                for (int r = 0; r < 4; r++) acc[q][mt][nt][r] = 0.f;

    for (int kt = 0; kt < 32; kt++) {
        int k0 = kt * 32;
        // A tile 128x32, tf32-quantized
#pragma unroll
        for (int p = 0; p < 4; p++) {
            int idx = p * 256 + tid;
            int row = idx >> 3;
            int col = (idx & 7) * 4;
            float4 v = *(const float4*)(Ab + (size_t)row * 1024 + k0 + col);
            As[row][col + 0] = tf32r(v.x); As[row][col + 1] = tf32r(v.y);
            As[row][col + 2] = tf32r(v.z); As[row][col + 3] = tf32r(v.w);
        }
        // B tiles 32x64 for both batches (transform + quantize)
#pragma unroll
        for (int q = 0; q < 2; q++) {
            const float* Bb = q ? Bb1 : Bb0;
#pragma unroll
            for (int p = 0; p < 2; p++) {
                int idx = p * 256 + tid;
                int row = idx >> 4;
                int col = (idx & 15) * 4;
                int n   = k0 + row;
                float4 v = *(const float4*)(Bb + (size_t)n * NKC + col);
                if (STAGE == 2) {
                    float a = g_a1[n], c = g_c1[n];
                    v.x = fmaxf(fmaf(a, v.x, c), 0.f);
                    v.y = fmaxf(fmaf(a, v.y, c), 0.f);
                    v.z = fmaxf(fmaf(a, v.z, c), 0.f);
                    v.w = fmaxf(fmaf(a, v.w, c), 0.f);
                }
                Bs[q][row][col + 0] = tf32r(v.x); Bs[q][row][col + 1] = tf32r(v.y);
                Bs[q][row][col + 2] = tf32r(v.z); Bs[q][row][col + 3] = tf32r(v.w);
            }
        }
        __syncthreads();

#pragma unroll
        for (int s = 0; s < 4; s++) {
            int kr = s * 8;
            uint32_t af[2][4];
#pragma unroll
            for (int mt = 0; mt < 2; mt++) {
                int o = warp_o * 32 + mt * 16;
                af[mt][0] = __float_as_uint(As[o + g    ][kr + tg    ]);
                af[mt][1] = __float_as_uint(As[o + g + 8][kr + tg    ]);
                af[mt][2] = __float_as_uint(As[o + g    ][kr + tg + 4]);
                af[mt][3] = __float_as_uint(As[o + g + 8][kr + tg + 4]);
            }
#pragma unroll
            for (int q = 0; q < 2; q++) {
                uint32_t bf[4][2];
#pragma unroll
                for (int nt = 0; nt < 4; nt++) {
                    int col = warp_n * 32 + nt * 8 + g;
                    bf[nt][0] = __float_as_uint(Bs[q][kr + tg    ][col]);
                    bf[nt][1] = __float_as_uint(Bs[q][kr + tg + 4][col]);
                }
#pragma unroll
                for (int mt = 0; mt < 2; mt++)
#pragma unroll
                    for (int nt = 0; nt < 4; nt++)
                        mma_tf32(acc[q][mt][nt], af[mt], bf[nt], acc[q][mt][nt]);
            }
        }
        __syncthreads();
    }

#pragma unroll
    for (int q = 0; q < 2; q++) {
        float* Cb = Cm + (size_t)(bz0 + q) * (NO * NKC) + (size_t)o0 * NKC + kc0;
#pragma unroll
        for (int mt = 0; mt < 2; mt++) {
            int row = warp_o * 32 + mt * 16 + g;
#pragma unroll
            for (int nt = 0; nt < 4; nt++) {
                int col = warp_n * 32 + nt * 8 + tg * 2;
                *(float2*)&Cb[(size_t)(row    ) * NKC + col] =
                    make_float2(acc[q][mt][nt][0], acc[q][mt][nt][1]);
                *(float2*)&Cb[(size_t)(row + 8) * NKC + col] =
                    make_float2(acc[q][mt][nt][2], acc[q][mt][nt][3]);
            }
        }
    }
}

// ---------------- BN stats per channel o: a = gamma*rsqrt(var+eps), c = beta - mean*a
__global__ void bn_stats_kernel(const float* __restrict__ gamma,
                                const float* __restrict__ beta, int which) {
    const float* Y = which ? g_y2 : g_y1;
    int o = blockIdx.x, tid = threadIdx.x;
    float s = 0.f, sq = 0.f;
    for (int j = tid; j < NB * NKC; j += 256) {
        int b = j / NKC, kc = j - b * NKC;
        float v = Y[((size_t)b * NO + o) * NKC + kc];
        s += v; sq = fmaf(v, v, sq);
    }
    __shared__ float ss[256], s2[256];
    ss[tid] = s; s2[tid] = sq;
    __syncthreads();
    for (int st = 128; st; st >>= 1) {
        if (tid < st) { ss[tid] += ss[tid + st]; s2[tid] += s2[tid + st]; }
        __syncthreads();
    }
    if (tid == 0) {
        float cnt  = (float)(NB * NKC);
        float mean = ss[0] / cnt;
        float var  = fmaxf(s2[0] / cnt - mean * mean, 0.f);
        float ai   = gamma[o] * rsqrtf(var + EPSN);
        if (which) { g_a2[o] = ai; g_c2[o] = beta[o] - mean * ai; }
        else       { g_a1[o] = ai; g_c1[o] = beta[o] - mean * ai; }
    }
}

// ---------------- out[b,o,c] = max_k relu(a2*y2 + c2) ----------------
__global__ void max_kernel(float* __restrict__ out) {
    int t = blockIdx.x * blockDim.x + threadIdx.x;
    int c = t & 63;
    int o = (t >> 6) & 1023;
    int b = t >> 16;
    const float* y = g_y2 + ((size_t)(b * NO + o)) * NKC + c;
    float a = g_a2[o], cc = g_c2[o];
    float m = -3.4e38f;
#pragma unroll
    for (int k = 0; k < NK; k++) m = fmaxf(m, fmaf(a, y[k * 64], cc));
    out[t] = fmaxf(m, 0.f);
}

// ---------------- launch ----------------
extern "C" void kernel_launch(void* const* d_in, const int* in_sizes, int n_in,
                              void* d_out, int out_size) {
    const float* x      = (const float*)d_in[0];
    const float* w1     = (const float*)d_in[1];
    // b1 = d_in[2], b2 = d_in[6]: zeros AND cancelled by BN mean-subtraction
    const float* gamma1 = (const float*)d_in[3];
    const float* beta1  = (const float*)d_in[4];
    const float* w2     = (const float*)d_in[5];
    const float* gamma2 = (const float*)d_in[7];
    const float* beta2  = (const float*)d_in[8];
    float* out = (float*)d_out;

    transpose_kernel<<<dim3(32, 2, 32), dim3(32, 8)>>>(x);
    xx_kernel<<<128, 256>>>(x);
    dist_kernel<<<dim3(136, 1, 32), 256>>>();
    topk_kernel<<<4096, 256>>>();
    gather_kernel<<<81920, 256>>>();
    gemm_mma_kernel<1><<<dim3(10, 8, 16), 256>>>(w1);
    bn_stats_kernel<<<1024, 256>>>(gamma1, beta1, 0);
    gemm_mma_kernel<2><<<dim3(10, 8, 16), 256>>>(w2);
    bn_stats_kernel<<<1024, 256>>>(gamma2, beta2, 1);
    max_kernel<<<8192, 256>>>(out);
}